// round 11
// baseline (speedup 1.0000x reference)
#include <cuda_runtime.h>
#include <cstdint>

#define BS    128
#define NT    25
#define MQ    1024
#define CREC  107
#define CLOC  25
#define THREADS 384
#define NWARP (THREADS / 32)
#define INFF  3.0e38f
#define PFREE 0x7fffffff

__device__ double   g_sums[BS * 2];
__device__ unsigned g_count;     // zero-init; reset by last block each launch

struct Smem {
  float  cost[NT][MQ];           // 100 KB (16B-aligned rows, stride 4KB)
  unsigned long long rkey[NT];   // packed (f2ord(rowmin)<<32)|argj
  float  u[NT + 1];
  int    p[MQ + 1];
  int    way[MQ + 1];            // indexed through swzw()
  int    tgt_cls[NT];
  int    match_q[NT];
  int    pend[NT];
  int    npend;
  double warp_rec[NWARP];
  double warp_loc[NWARP];
  int    islast;
  double red_r[4], red_l[4];
};

// focal cost via 3 MUFU (EX2, LG2, RCP). With t=e^{-x}, L=log(1+t):
//   focal = p^2 * (0.25*t^2*L - 0.75*(x+L)),  p = 1/(1+t).
__device__ __forceinline__ float focal_mufu(float x) {
  float t = __expf(-x);
  float w = 1.0f + t;
  float L = __logf(w);
  float p = __fdividef(1.0f, w);
  return p * p * (0.25f * t * t * L - 0.75f * (x + L));
}

__device__ __forceinline__ float warp_max_f(float v) {
  #pragma unroll
  for (int o = 16; o; o >>= 1) v = fmaxf(v, __shfl_xor_sync(0xffffffffu, v, o));
  return v;
}
__device__ __forceinline__ float warp_sum_f(float v) {
  #pragma unroll
  for (int o = 16; o; o >>= 1) v += __shfl_xor_sync(0xffffffffu, v, o);
  return v;
}

// float -> order-preserving uint (finite values only)
__device__ __forceinline__ unsigned f2ord(float v) {
  unsigned u = __float_as_uint(v);
  return (u & 0x80000000u) ? ~u : (u | 0x80000000u);
}
__device__ __forceinline__ float ord2f(unsigned s) {
  unsigned u = (s & 0x80000000u) ? (s & 0x7fffffffu) : ~s;
  return __uint_as_float(u);
}

// bank swizzle for way[]: bijective on [0,1024]; per-instruction conflict-free
__device__ __forceinline__ int swzw(int j) {
  return (j & ~31) | ((j + (j >> 5)) & 31);
}

__global__ __launch_bounds__(THREADS)
void rec_criterion_kernel(const float* __restrict__ rec,
                          const float* __restrict__ loc,
                          const int*   __restrict__ tgt32,
                          float* __restrict__ out) {
  extern __shared__ char smem_raw[];
  Smem& S = *reinterpret_cast<Smem*>(smem_raw);
  const int b   = blockIdx.x;
  const int tid = threadIdx.x;
  const int wid = tid >> 5, lane = tid & 31;

  // ---- startup: detection + target load (warp 0), p/rkey init, ONE barrier ----
  if (tid < 32) {
    int w = tgt32[2 * tid + 1];            // odd words of first 32 int64 slots
    unsigned bal = __ballot_sync(0xffffffffu, w != 0);
    bool is64 = (bal == 0u);
    if (tid < NT) {
      int t;
      if (is64) t = (int)(reinterpret_cast<const long long*>(tgt32)[b * NT + tid]);
      else      t = tgt32[b * NT + tid];
      S.tgt_cls[tid] = t;
      S.rkey[tid] = 0xFFFFFFFFFFFFFFFFull;
    }
  }
  for (int j = tid; j <= MQ; j += THREADS) S.p[j] = PFREE;
  __syncthreads();

  const float* recb = rec + (size_t)b * CREC * MQ;
  const float* locb = loc + (size_t)b * CLOC * MQ;

  // ---- Phase A: half-row items (50) over 12 warps; 3-MUFU focal; packed row-min ----
  for (int it = wid; it < 2 * NT; it += NWARP) {
    const int r = it >> 1, h = it & 1;
    const float4* rp = reinterpret_cast<const float4*>(recb + (size_t)S.tgt_cls[r] * MQ);
    const float4* lp = reinterpret_cast<const float4*>(locb + (size_t)r * MQ);
    float4* crow4 = reinterpret_cast<float4*>(&S.cost[r][0]);
    float m = INFF; int jb = 0;
    float4 rv[4], lv[4];
    #pragma unroll
    for (int k = 0; k < 4; k++) rv[k] = __ldg(rp + lane + ((h * 4 + k) << 5));
    #pragma unroll
    for (int k = 0; k < 4; k++) lv[k] = __ldg(lp + lane + ((h * 4 + k) << 5));
    #pragma unroll
    for (int k = 0; k < 4; k++) {
      int g = lane + ((h * 4 + k) << 5);       // float4 group; j = 4g..4g+3
      float4 c;
      c.x = fmaf(2.0f, focal_mufu(rv[k].x), focal_mufu(lv[k].x));
      c.y = fmaf(2.0f, focal_mufu(rv[k].y), focal_mufu(lv[k].y));
      c.z = fmaf(2.0f, focal_mufu(rv[k].z), focal_mufu(lv[k].z));
      c.w = fmaf(2.0f, focal_mufu(rv[k].w), focal_mufu(lv[k].w));
      crow4[g] = c;
      int j = g << 2;                           // ascending j per lane: first occurrence
      if (c.x < m) { m = c.x; jb = j; }
      if (c.y < m) { m = c.y; jb = j + 1; }
      if (c.z < m) { m = c.z; jb = j + 2; }
      if (c.w < m) { m = c.w; jb = j + 3; }
    }
    unsigned om = __reduce_min_sync(0xffffffffu, f2ord(m));
    float gm = ord2f(om);
    unsigned jc = (m == gm) ? (unsigned)jb : 0xffffffffu;
    unsigned jm = __reduce_min_sync(0xffffffffu, jc);
    if (lane == 0)
      atomicMin(&S.rkey[r], ((unsigned long long)om << 32) | (unsigned long long)jm);
  }
  __syncthreads();

  // ---- Phase B1: greedy init, parallel (atomicMin = first-row-wins) ----
  if (tid < 32) {
    bool has = tid < NT;
    int rarg = 0;
    if (has) {
      unsigned long long key = S.rkey[tid];
      rarg = (int)(key & 0xffffffffu);
      S.u[tid + 1] = ord2f((unsigned)(key >> 32));
      atomicMin(&S.p[rarg + 1], tid + 1);
    }
    if (tid == 0) S.u[0] = 0.0f;
    __syncwarp();
    bool lost = has && (S.p[rarg + 1] != tid + 1);
    unsigned mask = __ballot_sync(0xffffffffu, lost);
    if (lost) S.pend[__popc(mask & ((1u << tid) - 1u))] = tid + 1;  // ascending rows
    if (tid == 0) S.npend = __popc(mask);
  }
  __syncthreads();

  // ---- Phase B2: Dijkstra for contested rows (warp 0, deferred duals, v0=0) ----
  // Lane owns contiguous cols j in [32*lane+1, 32*lane+32]; slot k: j = jb0 + k.
  if (tid < 32) {
    const int jb0 = (lane << 5) + 1;
    float v_r[32];
    #pragma unroll
    for (int k = 0; k < 32; k++) v_r[k] = 0.0f;
    const int np = S.npend;

    for (int pi = 0; pi < np; pi++) {
      const int i = S.pend[pi];
      float minv_r[32];
      #pragma unroll
      for (int k = 0; k < 32; k++) minv_r[k] = INFF;
      unsigned usedmask = 0u;
      float D = 0.0f;
      int j0 = 0;

      while (true) {
        if (j0 > 0) {
          int idx = j0 - 1;
          if ((idx >> 5) == lane) usedmask |= 1u << (idx & 31);
        }
        const int   i0  = (j0 == 0) ? i : S.p[j0];
        const float u0p = S.u[i0] - D;
        const float4* crow4 =
            reinterpret_cast<const float4*>(&S.cost[i0 - 1][0]) + (lane << 3);

        // 8x LDS.128 scan; 4 (value,idx) accumulators; strict < = first occurrence
        float bv0 = INFF, bv1 = INFF, bv2 = INFF, bv3 = INFF;
        int   bk0 = 0,    bk1 = 0,    bk2 = 0,    bk3 = 0;
        #pragma unroll
        for (int q = 0; q < 8; q++) {
          float4 cv = crow4[q];
          const int kq = q << 2;
          {
            int k = kq;     bool used = (usedmask >> k) & 1u;
            float cur = (cv.x - u0p) - v_r[k];
            cur = used ? INFF : cur;
            if (cur < minv_r[k]) { S.way[swzw(jb0 + k)] = j0; minv_r[k] = cur; }
            float mv = used ? INFF : minv_r[k];
            if (mv < bv0) { bv0 = mv; bk0 = k; }
          }
          {
            int k = kq + 1; bool used = (usedmask >> k) & 1u;
            float cur = (cv.y - u0p) - v_r[k];
            cur = used ? INFF : cur;
            if (cur < minv_r[k]) { S.way[swzw(jb0 + k)] = j0; minv_r[k] = cur; }
            float mv = used ? INFF : minv_r[k];
            if (mv < bv1) { bv1 = mv; bk1 = k; }
          }
          {
            int k = kq + 2; bool used = (usedmask >> k) & 1u;
            float cur = (cv.z - u0p) - v_r[k];
            cur = used ? INFF : cur;
            if (cur < minv_r[k]) { S.way[swzw(jb0 + k)] = j0; minv_r[k] = cur; }
            float mv = used ? INFF : minv_r[k];
            if (mv < bv2) { bv2 = mv; bk2 = k; }
          }
          {
            int k = kq + 3; bool used = (usedmask >> k) & 1u;
            float cur = (cv.w - u0p) - v_r[k];
            cur = used ? INFF : cur;
            if (cur < minv_r[k]) { S.way[swzw(jb0 + k)] = j0; minv_r[k] = cur; }
            float mv = used ? INFF : minv_r[k];
            if (mv < bv3) { bv3 = mv; bk3 = k; }
          }
        }
        // merge 4 pairs, tie -> smaller k (np.argmin first-occurrence)
        float bv = bv0; int bk = bk0;
        if (bv1 < bv || (bv1 == bv && bk1 < bk)) { bv = bv1; bk = bk1; }
        if (bv2 < bv || (bv2 == bv && bk2 < bk)) { bv = bv2; bk = bk2; }
        if (bv3 < bv || (bv3 == bv && bk3 < bk)) { bv = bv3; bk = bk3; }

        unsigned om = __reduce_min_sync(0xffffffffu, f2ord(bv));
        float gm = ord2f(om);
        // lane-j ordering == global-j ordering (contiguous blocks per lane)
        unsigned jl = (bv == gm) ? (unsigned)(jb0 + bk) : 0xffffffffu;
        unsigned jm = __reduce_min_sync(0xffffffffu, jl);
        D  = gm;
        j0 = (int)jm;
        if (S.p[j0] == PFREE) break;   // free column reached
      }

      const float Dend = D;
      __syncwarp();                    // way[] stores visible
      unsigned mm = usedmask;
      while (mm) {
        int k = __ffs(mm) - 1; mm &= mm - 1;
        float dv = Dend - minv_r[k];
        v_r[k] -= dv;
        S.u[S.p[jb0 + k]] += dv;       // distinct rows per used col -> race-free
      }
      if (lane == 0) { S.u[i] += Dend; S.p[0] = i; }
      __syncwarp();
      if (lane == 0) {                 // augment through swizzled way[]
        int j = j0;
        while (j != 0) { int jp = S.way[swzw(j)]; S.p[j] = S.p[jp]; j = jp; }
      }
      __syncwarp();
    }
    // deterministic match collection
    #pragma unroll
    for (int k = 0; k < 32; k++) {
      int r = S.p[jb0 + k];
      if (r != PFREE) S.match_q[r - 1] = jb0 + k - 1;
    }
  }
  __syncthreads();

  // ---- Phase C: CE over matched pairs, warp-per-match, fast intrinsics ----
  if (lane == 0) { S.warp_rec[wid] = 0.0; S.warp_loc[wid] = 0.0; }
  __syncwarp();

  for (int t = wid; t < NT; t += NWARP) {
    const int q = S.match_q[t];

    // rec CE: 107 channels, 4 per lane, loaded once
    const float* rb = recb + q;
    float v4[4];
    #pragma unroll
    for (int k = 0; k < 4; k++) {
      int c = lane + (k << 5);
      v4[k] = (c < CREC) ? __ldg(rb + (size_t)c * MQ) : -INFF;
    }
    float mx = fmaxf(fmaxf(v4[0], v4[1]), fmaxf(v4[2], v4[3]));
    mx = warp_max_f(mx);
    float se = 0.f;
    #pragma unroll
    for (int k = 0; k < 4; k++) {
      int c = lane + (k << 5);
      if (c < CREC) se += __expf(v4[k] - mx);
    }
    se = warp_sum_f(se);
    float rec_term = mx + __logf(se) - __ldg(rb + (size_t)S.tgt_cls[t] * MQ);

    // loc CE: 25 channels
    const float* lb = locb + q;
    float xv  = (lane < CLOC) ? __ldg(lb + (size_t)lane * MQ) : -INFF;
    float mx2 = warp_max_f(xv);
    float se2 = warp_sum_f((lane < CLOC) ? __expf(xv - mx2) : 0.f);
    float loc_term = mx2 + __logf(se2) - __ldg(lb + (size_t)t * MQ);

    if (lane == 0) {
      S.warp_rec[wid] += (double)rec_term;
      S.warp_loc[wid] += (double)loc_term;
    }
  }
  __syncthreads();

  // ---- per-batch sums + last-block final reduction ----
  if (tid == 0) {
    double r = 0.0, l = 0.0;
    #pragma unroll
    for (int w = 0; w < NWARP; w++) { r += S.warp_rec[w]; l += S.warp_loc[w]; }
    g_sums[2 * b]     = r;
    g_sums[2 * b + 1] = l;
    __threadfence();
    unsigned old = atomicAdd(&g_count, 1u);
    S.islast = (old == BS - 1);
  }
  __syncthreads();

  if (S.islast) {
    double r = (tid < BS) ? g_sums[2 * tid]     : 0.0;
    double l = (tid < BS) ? g_sums[2 * tid + 1] : 0.0;
    #pragma unroll
    for (int o = 16; o; o >>= 1) {
      r += __shfl_xor_sync(0xffffffffu, r, o);
      l += __shfl_xor_sync(0xffffffffu, l, o);
    }
    if (lane == 0 && wid < 4) { S.red_r[wid] = r; S.red_l[wid] = l; }
    __syncthreads();
    if (tid == 0) {
      double rr = S.red_r[0] + S.red_r[1] + S.red_r[2] + S.red_r[3];
      double ll = S.red_l[0] + S.red_l[1] + S.red_l[2] + S.red_l[3];
      out[0] = (float)(rr / (double)(BS * NT));
      out[1] = (float)(ll / (double)(BS * NT));
      g_count = 0;   // reset for next replay
    }
  }
}

extern "C" void kernel_launch(void* const* d_in, const int* in_sizes, int n_in,
                              void* d_out, int out_size) {
  const float* rec = (const float*)d_in[0];
  const float* loc = (const float*)d_in[1];
  const int*   tgt = (const int*)d_in[2];
  float* out = (float*)d_out;

  const int smem = (int)sizeof(Smem);
  cudaFuncSetAttribute(rec_criterion_kernel,
                       cudaFuncAttributeMaxDynamicSharedMemorySize, smem);
  rec_criterion_kernel<<<BS, THREADS, smem>>>(rec, loc, tgt, out);
}

// round 12
// speedup vs baseline: 1.3101x; 1.3101x over previous
#include <cuda_runtime.h>
#include <cstdint>

#define BS    128
#define NT    25
#define MQ    1024
#define CREC  107
#define CLOC  25
#define THREADS 512
#define NWARP (THREADS / 32)
#define INFF  3.0e38f
#define PFREE 0x7fffffff

__device__ double   g_sums[BS * 2];
__device__ unsigned g_count;     // zero-init; reset by last block each launch

struct Smem {
  float  cost[NT][MQ];           // 100 KB
  float  u[NT + 1];
  int    p[MQ + 1];
  int    way[MQ + 1];
  unsigned long long wkey[2][4]; // per-warp argmin keys, double-buffered by parity
  int    tgt_cls[NT];
  int    match_q[NT];
  float  rmin[NT];
  int    rarg[NT];
  int    pend[NT];
  int    npend;
  int    is64;
  double warp_rec[NWARP];
  double warp_loc[NWARP];
  int    islast;
  double red_r[4], red_l[4];
};

// focal cost via 3 MUFU (EX2, LG2, RCP). With t=e^{-x}, L=log(1+t):
//   focal = p^2 * (0.25*t^2*L - 0.75*(x+L)),  p = 1/(1+t).
__device__ __forceinline__ float focal_mufu(float x) {
  float t = __expf(-x);
  float w = 1.0f + t;
  float L = __logf(w);
  float p = __fdividef(1.0f, w);
  return p * p * (0.25f * t * t * L - 0.75f * (x + L));
}

__device__ __forceinline__ float warp_max_f(float v) {
  #pragma unroll
  for (int o = 16; o; o >>= 1) v = fmaxf(v, __shfl_xor_sync(0xffffffffu, v, o));
  return v;
}
__device__ __forceinline__ float warp_sum_f(float v) {
  #pragma unroll
  for (int o = 16; o; o >>= 1) v += __shfl_xor_sync(0xffffffffu, v, o);
  return v;
}

// float -> order-preserving uint (finite values only)
__device__ __forceinline__ unsigned f2ord(float v) {
  unsigned u = __float_as_uint(v);
  return (u & 0x80000000u) ? ~u : (u | 0x80000000u);
}
__device__ __forceinline__ float ord2f(unsigned s) {
  unsigned u = (s & 0x80000000u) ? (s & 0x7fffffffu) : ~s;
  return __uint_as_float(u);
}

__device__ __forceinline__ void bar_wg(int id) {
  asm volatile("bar.sync %0, 128;" :: "r"(id) : "memory");
}

__global__ __launch_bounds__(THREADS)
void rec_criterion_kernel(const float* __restrict__ rec,
                          const float* __restrict__ loc,
                          const int*   __restrict__ tgt32,
                          float* __restrict__ out) {
  extern __shared__ char smem_raw[];
  Smem& S = *reinterpret_cast<Smem*>(smem_raw);
  const int b   = blockIdx.x;
  const int tid = threadIdx.x;
  const int wid = tid >> 5, lane = tid & 31;

  // ---- detection (warp 0) + init ----
  if (tid < 32) {
    int w = tgt32[2 * tid + 1];            // odd words of first 32 int64 slots
    unsigned bal = __ballot_sync(0xffffffffu, w != 0);
    if (tid == 0) S.is64 = (bal == 0u);
  }
  for (int j = tid; j <= MQ; j += THREADS) S.p[j] = PFREE;
  __syncthreads();

  if (tid < NT) {
    int t;
    if (S.is64) t = (int)(reinterpret_cast<const long long*>(tgt32)[b * NT + tid]);
    else        t = tgt32[b * NT + tid];
    S.tgt_cls[tid] = t;
  }
  __syncthreads();

  const float* recb = rec + (size_t)b * CREC * MQ;
  const float* locb = loc + (size_t)b * CLOC * MQ;

  // ---- Phase A (+fused row-min): warp-per-row, float4, 16 warps ----
  for (int r = wid; r < NT; r += NWARP) {
    const float4* rp = reinterpret_cast<const float4*>(recb + (size_t)S.tgt_cls[r] * MQ);
    const float4* lp = reinterpret_cast<const float4*>(locb + (size_t)r * MQ);
    float4* crow4 = reinterpret_cast<float4*>(&S.cost[r][0]);
    float m = INFF; int jb = 0;
    #pragma unroll
    for (int h = 0; h < 2; h++) {
      float4 rv[4], lv[4];
      #pragma unroll
      for (int k = 0; k < 4; k++) rv[k] = __ldg(rp + lane + ((h * 4 + k) << 5));
      #pragma unroll
      for (int k = 0; k < 4; k++) lv[k] = __ldg(lp + lane + ((h * 4 + k) << 5));
      #pragma unroll
      for (int k = 0; k < 4; k++) {
        int g = lane + ((h * 4 + k) << 5);      // float4 group; j = 4g..4g+3
        float4 c;
        c.x = fmaf(2.0f, focal_mufu(rv[k].x), focal_mufu(lv[k].x));
        c.y = fmaf(2.0f, focal_mufu(rv[k].y), focal_mufu(lv[k].y));
        c.z = fmaf(2.0f, focal_mufu(rv[k].z), focal_mufu(lv[k].z));
        c.w = fmaf(2.0f, focal_mufu(rv[k].w), focal_mufu(lv[k].w));
        crow4[g] = c;
        int j = g << 2;                          // ascending j per lane: first occurrence
        if (c.x < m) { m = c.x; jb = j; }
        if (c.y < m) { m = c.y; jb = j + 1; }
        if (c.z < m) { m = c.z; jb = j + 2; }
        if (c.w < m) { m = c.w; jb = j + 3; }
      }
    }
    unsigned om = __reduce_min_sync(0xffffffffu, f2ord(m));
    float gm = ord2f(om);
    unsigned jc = (m == gm) ? (unsigned)jb : 0xffffffffu;
    unsigned jm = __reduce_min_sync(0xffffffffu, jc);
    if (lane == 0) { S.rmin[r] = gm; S.rarg[r] = (int)jm; }
  }
  __syncthreads();

  // ---- Phase B1: greedy init, parallel (atomicMin = first-row-wins) ----
  if (tid < 32) {
    bool has = tid < NT;
    int rarg = 0;
    if (has) {
      rarg = S.rarg[tid];
      S.u[tid + 1] = S.rmin[tid];
      atomicMin(&S.p[rarg + 1], tid + 1);
    }
    if (tid == 0) S.u[0] = 0.0f;
    __syncwarp();
    bool lost = has && (S.p[rarg + 1] != tid + 1);
    unsigned mask = __ballot_sync(0xffffffffu, lost);
    if (lost) S.pend[__popc(mask & ((1u << tid) - 1u))] = tid + 1;  // ascending rows
    if (tid == 0) S.npend = __popc(mask);
  }
  __syncthreads();

  // ---- Phase B2: Dijkstra for contested rows — 4-warp workgroup (tids 0-127) ----
  // tid owns 8 contiguous cols j in [8*tid+1, 8*tid+8]; j-order == (tid,k)-order.
  if (tid < 128) {
    const int jb0 = (tid << 3) + 1;
    float v_r[8];
    #pragma unroll
    for (int k = 0; k < 8; k++) v_r[k] = 0.0f;
    const int np = S.npend;

    for (int pi = 0; pi < np; pi++) {
      const int i = S.pend[pi];
      float minv_r[8];
      #pragma unroll
      for (int k = 0; k < 8; k++) minv_r[k] = INFF;
      unsigned usedmask = 0u;
      float D = 0.0f;
      int j0 = 0;
      int it = 0;

      while (true) {
        if (j0 > 0 && ((j0 - 1) >> 3) == tid) usedmask |= 1u << ((j0 - 1) & 7);

        const int   i0  = (j0 == 0) ? i : S.p[j0];
        const float u0p = S.u[i0] - D;
        const float4* crow4 =
            reinterpret_cast<const float4*>(&S.cost[i0 - 1][0]) + (tid << 1);

        float bv = INFF; int bk = 0;
        #pragma unroll
        for (int q = 0; q < 2; q++) {
          float4 cv = crow4[q];
          const int kq = q << 2;
          {
            int k = kq;     bool used = (usedmask >> k) & 1u;
            float cur = (cv.x - u0p) - v_r[k];
            cur = used ? INFF : cur;
            if (cur < minv_r[k]) { S.way[jb0 + k] = j0; minv_r[k] = cur; }
            float mv = used ? INFF : minv_r[k];
            if (mv < bv) { bv = mv; bk = k; }
          }
          {
            int k = kq + 1; bool used = (usedmask >> k) & 1u;
            float cur = (cv.y - u0p) - v_r[k];
            cur = used ? INFF : cur;
            if (cur < minv_r[k]) { S.way[jb0 + k] = j0; minv_r[k] = cur; }
            float mv = used ? INFF : minv_r[k];
            if (mv < bv) { bv = mv; bk = k; }
          }
          {
            int k = kq + 2; bool used = (usedmask >> k) & 1u;
            float cur = (cv.z - u0p) - v_r[k];
            cur = used ? INFF : cur;
            if (cur < minv_r[k]) { S.way[jb0 + k] = j0; minv_r[k] = cur; }
            float mv = used ? INFF : minv_r[k];
            if (mv < bv) { bv = mv; bk = k; }
          }
          {
            int k = kq + 3; bool used = (usedmask >> k) & 1u;
            float cur = (cv.w - u0p) - v_r[k];
            cur = used ? INFF : cur;
            if (cur < minv_r[k]) { S.way[jb0 + k] = j0; minv_r[k] = cur; }
            float mv = used ? INFF : minv_r[k];
            if (mv < bv) { bv = mv; bk = k; }
          }
        }
        // warp argmin (value, then smallest j)
        unsigned ov = f2ord(bv);
        unsigned om = __reduce_min_sync(0xffffffffu, ov);
        unsigned jl = (ov == om) ? (unsigned)(jb0 + bk) : 0xffffffffu;
        unsigned jm = __reduce_min_sync(0xffffffffu, jl);
        const int par = it & 1;
        if (lane == 0)
          S.wkey[par][wid] = ((unsigned long long)om << 32) | (unsigned long long)jm;
        bar_wg(7);
        // all 128 threads redundantly min the 4 keys (u64 min = value then min-j)
        unsigned long long k0 = S.wkey[par][0], k1 = S.wkey[par][1];
        unsigned long long k2 = S.wkey[par][2], k3 = S.wkey[par][3];
        unsigned long long km = k0 < k1 ? k0 : k1;
        if (k2 < km) km = k2;
        if (k3 < km) km = k3;
        D  = ord2f((unsigned)(km >> 32));
        j0 = (int)(km & 0xffffffffu);
        it++;
        if (S.p[j0] == PFREE) break;   // free column reached (all threads agree)
      }

      const float Dend = D;
      // fixups: used col j entered the tree at absolute distance minv_r[k]
      unsigned mm = usedmask;
      while (mm) {
        int k = __ffs(mm) - 1; mm &= mm - 1;
        float dv = Dend - minv_r[k];
        v_r[k] -= dv;
        S.u[S.p[jb0 + k]] += dv;       // distinct rows per used col -> race-free
      }
      if (tid == 0) S.u[i] += Dend;
      bar_wg(7);                        // fixup reads of p done before augment writes
      if (tid == 0) {
        S.p[0] = i;
        int j = j0;
        while (j != 0) { int jp = S.way[j]; S.p[j] = S.p[jp]; j = jp; }
      }
      bar_wg(7);                        // p visible before next Dijkstra
    }
    // deterministic match collection
    #pragma unroll
    for (int k = 0; k < 8; k++) {
      int r = S.p[jb0 + k];
      if (r != PFREE && r > 0) S.match_q[r - 1] = jb0 + k - 1;
    }
  }
  __syncthreads();

  // ---- Phase C: CE over matched pairs, warp-per-match, fast intrinsics ----
  if (lane == 0) { S.warp_rec[wid] = 0.0; S.warp_loc[wid] = 0.0; }
  __syncwarp();

  for (int t = wid; t < NT; t += NWARP) {
    const int q = S.match_q[t];

    // rec CE: 107 channels, 4 per lane, loaded once
    const float* rb = recb + q;
    float v4[4];
    #pragma unroll
    for (int k = 0; k < 4; k++) {
      int c = lane + (k << 5);
      v4[k] = (c < CREC) ? __ldg(rb + (size_t)c * MQ) : -INFF;
    }
    float mx = fmaxf(fmaxf(v4[0], v4[1]), fmaxf(v4[2], v4[3]));
    mx = warp_max_f(mx);
    float se = 0.f;
    #pragma unroll
    for (int k = 0; k < 4; k++) {
      int c = lane + (k << 5);
      if (c < CREC) se += __expf(v4[k] - mx);
    }
    se = warp_sum_f(se);
    float rec_term = mx + __logf(se) - __ldg(rb + (size_t)S.tgt_cls[t] * MQ);

    // loc CE: 25 channels
    const float* lb = locb + q;
    float xv  = (lane < CLOC) ? __ldg(lb + (size_t)lane * MQ) : -INFF;
    float mx2 = warp_max_f(xv);
    float se2 = warp_sum_f((lane < CLOC) ? __expf(xv - mx2) : 0.f);
    float loc_term = mx2 + __logf(se2) - __ldg(lb + (size_t)t * MQ);

    if (lane == 0) {
      S.warp_rec[wid] += (double)rec_term;
      S.warp_loc[wid] += (double)loc_term;
    }
  }
  __syncthreads();

  // ---- per-batch sums + last-block final reduction ----
  if (tid == 0) {
    double r = 0.0, l = 0.0;
    #pragma unroll
    for (int w = 0; w < NWARP; w++) { r += S.warp_rec[w]; l += S.warp_loc[w]; }
    g_sums[2 * b]     = r;
    g_sums[2 * b + 1] = l;
    __threadfence();
    unsigned old = atomicAdd(&g_count, 1u);
    S.islast = (old == BS - 1);
  }
  __syncthreads();

  if (S.islast) {
    double r = (tid < BS) ? g_sums[2 * tid]     : 0.0;
    double l = (tid < BS) ? g_sums[2 * tid + 1] : 0.0;
    #pragma unroll
    for (int o = 16; o; o >>= 1) {
      r += __shfl_xor_sync(0xffffffffu, r, o);
      l += __shfl_xor_sync(0xffffffffu, l, o);
    }
    if (lane == 0 && wid < 4) { S.red_r[wid] = r; S.red_l[wid] = l; }
    __syncthreads();
    if (tid == 0) {
      double rr = S.red_r[0] + S.red_r[1] + S.red_r[2] + S.red_r[3];
      double ll = S.red_l[0] + S.red_l[1] + S.red_l[2] + S.red_l[3];
      out[0] = (float)(rr / (double)(BS * NT));
      out[1] = (float)(ll / (double)(BS * NT));
      g_count = 0;   // reset for next replay
    }
  }
}

extern "C" void kernel_launch(void* const* d_in, const int* in_sizes, int n_in,
                              void* d_out, int out_size) {
  const float* rec = (const float*)d_in[0];
  const float* loc = (const float*)d_in[1];
  const int*   tgt = (const int*)d_in[2];
  float* out = (float*)d_out;

  const int smem = (int)sizeof(Smem);
  cudaFuncSetAttribute(rec_criterion_kernel,
                       cudaFuncAttributeMaxDynamicSharedMemorySize, smem);
  rec_criterion_kernel<<<BS, THREADS, smem>>>(rec, loc, tgt, out);
}

// round 13
// speedup vs baseline: 1.3164x; 1.0047x over previous
#include <cuda_runtime.h>
#include <cstdint>

#define BS    128
#define NT    25
#define MQ    1024
#define CREC  107
#define CLOC  25
#define THREADS 768
#define NWARP (THREADS / 32)
#define INFF  3.0e38f
#define PFREE 0x7fffffff

__device__ double   g_sums[BS * 2];
__device__ unsigned g_count;     // zero-init; reset by last block each launch

struct Smem {
  float  cost[NT][MQ];           // 100 KB
  unsigned long long rkey[NT];   // packed (f2ord(rowmin)<<32)|argj
  float  u[NT + 1];
  int    p[MQ + 1];
  int    way[MQ + 1];
  unsigned long long wkey[2][4]; // per-warp argmin keys, double-buffered by parity
  int    tgt_cls[NT];
  int    match_q[NT];
  int    pend[NT];
  int    npend;
  int    is64;
  double warp_rec[NWARP];
  double warp_loc[NWARP];
  int    islast;
  double red_r[8], red_l[8];
};

// focal cost via 3 MUFU (EX2, LG2, RCP). With t=e^{-x}, L=log(1+t):
//   focal = p^2 * (0.25*t^2*L - 0.75*(x+L)),  p = 1/(1+t).
__device__ __forceinline__ float focal_mufu(float x) {
  float t = __expf(-x);
  float w = 1.0f + t;
  float L = __logf(w);
  float p = __fdividef(1.0f, w);
  return p * p * (0.25f * t * t * L - 0.75f * (x + L));
}

__device__ __forceinline__ float warp_max_f(float v) {
  #pragma unroll
  for (int o = 16; o; o >>= 1) v = fmaxf(v, __shfl_xor_sync(0xffffffffu, v, o));
  return v;
}
__device__ __forceinline__ float warp_sum_f(float v) {
  #pragma unroll
  for (int o = 16; o; o >>= 1) v += __shfl_xor_sync(0xffffffffu, v, o);
  return v;
}

// float -> order-preserving uint (finite values only)
__device__ __forceinline__ unsigned f2ord(float v) {
  unsigned u = __float_as_uint(v);
  return (u & 0x80000000u) ? ~u : (u | 0x80000000u);
}
__device__ __forceinline__ float ord2f(unsigned s) {
  unsigned u = (s & 0x80000000u) ? (s & 0x7fffffffu) : ~s;
  return __uint_as_float(u);
}

__device__ __forceinline__ void bar_wg(int id) {
  asm volatile("bar.sync %0, 128;" :: "r"(id) : "memory");
}

__global__ __launch_bounds__(THREADS, 1)
void rec_criterion_kernel(const float* __restrict__ rec,
                          const float* __restrict__ loc,
                          const int*   __restrict__ tgt32,
                          float* __restrict__ out) {
  extern __shared__ char smem_raw[];
  Smem& S = *reinterpret_cast<Smem*>(smem_raw);
  const int b   = blockIdx.x;
  const int tid = threadIdx.x;
  const int wid = tid >> 5, lane = tid & 31;

  // ---- detection (warp 0) + init ----
  if (tid < 32) {
    int w = tgt32[2 * tid + 1];            // odd words of first 32 int64 slots
    unsigned bal = __ballot_sync(0xffffffffu, w != 0);
    if (tid == 0) S.is64 = (bal == 0u);
  }
  for (int j = tid; j <= MQ; j += THREADS) S.p[j] = PFREE;
  if (tid < NT) S.rkey[tid] = 0xFFFFFFFFFFFFFFFFull;
  __syncthreads();

  if (tid < NT) {
    int t;
    if (S.is64) t = (int)(reinterpret_cast<const long long*>(tgt32)[b * NT + tid]);
    else        t = tgt32[b * NT + tid];
    S.tgt_cls[tid] = t;
  }
  __syncthreads();

  const float* recb = rec + (size_t)b * CREC * MQ;
  const float* locb = loc + (size_t)b * CLOC * MQ;

  // ---- Phase A: half-row items (50) over 24 warps; float4; packed row-min ----
  for (int it = wid; it < 2 * NT; it += NWARP) {
    const int r = it >> 1, h = it & 1;
    const float4* rp = reinterpret_cast<const float4*>(recb + (size_t)S.tgt_cls[r] * MQ);
    const float4* lp = reinterpret_cast<const float4*>(locb + (size_t)r * MQ);
    float4* crow4 = reinterpret_cast<float4*>(&S.cost[r][0]);
    float m = INFF; int jb = 0;
    float4 rv[4], lv[4];
    #pragma unroll
    for (int k = 0; k < 4; k++) rv[k] = __ldg(rp + lane + ((h * 4 + k) << 5));
    #pragma unroll
    for (int k = 0; k < 4; k++) lv[k] = __ldg(lp + lane + ((h * 4 + k) << 5));
    #pragma unroll
    for (int k = 0; k < 4; k++) {
      int g = lane + ((h * 4 + k) << 5);       // float4 group; j = 4g..4g+3
      float4 c;
      c.x = fmaf(2.0f, focal_mufu(rv[k].x), focal_mufu(lv[k].x));
      c.y = fmaf(2.0f, focal_mufu(rv[k].y), focal_mufu(lv[k].y));
      c.z = fmaf(2.0f, focal_mufu(rv[k].z), focal_mufu(lv[k].z));
      c.w = fmaf(2.0f, focal_mufu(rv[k].w), focal_mufu(lv[k].w));
      crow4[g] = c;
      int j = g << 2;                           // ascending j per lane: first occurrence
      if (c.x < m) { m = c.x; jb = j; }
      if (c.y < m) { m = c.y; jb = j + 1; }
      if (c.z < m) { m = c.z; jb = j + 2; }
      if (c.w < m) { m = c.w; jb = j + 3; }
    }
    unsigned om = __reduce_min_sync(0xffffffffu, f2ord(m));
    float gm = ord2f(om);
    unsigned jc = (m == gm) ? (unsigned)jb : 0xffffffffu;
    unsigned jm = __reduce_min_sync(0xffffffffu, jc);
    if (lane == 0)
      atomicMin(&S.rkey[r], ((unsigned long long)om << 32) | (unsigned long long)jm);
  }
  __syncthreads();

  // ---- Phase B1: greedy init, parallel (atomicMin = first-row-wins) ----
  if (tid < 32) {
    bool has = tid < NT;
    int rarg = 0;
    if (has) {
      unsigned long long key = S.rkey[tid];
      rarg = (int)(key & 0xffffffffu);
      S.u[tid + 1] = ord2f((unsigned)(key >> 32));
      atomicMin(&S.p[rarg + 1], tid + 1);
    }
    if (tid == 0) S.u[0] = 0.0f;
    __syncwarp();
    bool lost = has && (S.p[rarg + 1] != tid + 1);
    unsigned mask = __ballot_sync(0xffffffffu, lost);
    if (lost) S.pend[__popc(mask & ((1u << tid) - 1u))] = tid + 1;  // ascending rows
    if (tid == 0) S.npend = __popc(mask);
  }
  __syncthreads();

  // ---- Phase B2: Dijkstra for contested rows — 4-warp workgroup (tids 0-127) ----
  // tid owns 8 contiguous cols j in [8*tid+1, 8*tid+8]; j-order == (tid,k)-order.
  if (tid < 128) {
    const int jb0 = (tid << 3) + 1;
    float v_r[8];
    #pragma unroll
    for (int k = 0; k < 8; k++) v_r[k] = 0.0f;
    const int np = S.npend;

    for (int pi = 0; pi < np; pi++) {
      const int i = S.pend[pi];
      float minv_r[8];
      #pragma unroll
      for (int k = 0; k < 8; k++) minv_r[k] = INFF;
      unsigned usedmask = 0u;
      float D = 0.0f;
      int j0 = 0;
      int it = 0;

      while (true) {
        if (j0 > 0 && ((j0 - 1) >> 3) == tid) usedmask |= 1u << ((j0 - 1) & 7);

        const int   i0  = (j0 == 0) ? i : S.p[j0];
        const float u0p = S.u[i0] - D;
        const float4* crow4 =
            reinterpret_cast<const float4*>(&S.cost[i0 - 1][0]) + (tid << 1);

        float bv = INFF; int bk = 0;
        #pragma unroll
        for (int q = 0; q < 2; q++) {
          float4 cv = crow4[q];
          const int kq = q << 2;
          {
            int k = kq;     bool used = (usedmask >> k) & 1u;
            float cur = (cv.x - u0p) - v_r[k];
            cur = used ? INFF : cur;
            if (cur < minv_r[k]) { S.way[jb0 + k] = j0; minv_r[k] = cur; }
            float mv = used ? INFF : minv_r[k];
            if (mv < bv) { bv = mv; bk = k; }
          }
          {
            int k = kq + 1; bool used = (usedmask >> k) & 1u;
            float cur = (cv.y - u0p) - v_r[k];
            cur = used ? INFF : cur;
            if (cur < minv_r[k]) { S.way[jb0 + k] = j0; minv_r[k] = cur; }
            float mv = used ? INFF : minv_r[k];
            if (mv < bv) { bv = mv; bk = k; }
          }
          {
            int k = kq + 2; bool used = (usedmask >> k) & 1u;
            float cur = (cv.z - u0p) - v_r[k];
            cur = used ? INFF : cur;
            if (cur < minv_r[k]) { S.way[jb0 + k] = j0; minv_r[k] = cur; }
            float mv = used ? INFF : minv_r[k];
            if (mv < bv) { bv = mv; bk = k; }
          }
          {
            int k = kq + 3; bool used = (usedmask >> k) & 1u;
            float cur = (cv.w - u0p) - v_r[k];
            cur = used ? INFF : cur;
            if (cur < minv_r[k]) { S.way[jb0 + k] = j0; minv_r[k] = cur; }
            float mv = used ? INFF : minv_r[k];
            if (mv < bv) { bv = mv; bk = k; }
          }
        }
        // warp argmin (value, then smallest j)
        unsigned ov = f2ord(bv);
        unsigned om = __reduce_min_sync(0xffffffffu, ov);
        unsigned jl = (ov == om) ? (unsigned)(jb0 + bk) : 0xffffffffu;
        unsigned jm = __reduce_min_sync(0xffffffffu, jl);
        const int par = it & 1;
        if (lane == 0)
          S.wkey[par][wid] = ((unsigned long long)om << 32) | (unsigned long long)jm;
        bar_wg(7);
        // all 128 threads redundantly min the 4 keys (u64 min = value then min-j)
        unsigned long long k0 = S.wkey[par][0], k1 = S.wkey[par][1];
        unsigned long long k2 = S.wkey[par][2], k3 = S.wkey[par][3];
        unsigned long long km = k0 < k1 ? k0 : k1;
        if (k2 < km) km = k2;
        if (k3 < km) km = k3;
        D  = ord2f((unsigned)(km >> 32));
        j0 = (int)(km & 0xffffffffu);
        it++;
        if (S.p[j0] == PFREE) break;   // free column reached (all threads agree)
      }

      const float Dend = D;
      // fixups: used col j entered the tree at absolute distance minv_r[k]
      unsigned mm = usedmask;
      while (mm) {
        int k = __ffs(mm) - 1; mm &= mm - 1;
        float dv = Dend - minv_r[k];
        v_r[k] -= dv;
        S.u[S.p[jb0 + k]] += dv;       // distinct rows per used col -> race-free
      }
      if (tid == 0) S.u[i] += Dend;
      bar_wg(7);                        // fixup reads of p done before augment writes
      if (tid == 0) {
        S.p[0] = i;
        int j = j0;
        while (j != 0) { int jp = S.way[j]; S.p[j] = S.p[jp]; j = jp; }
      }
      bar_wg(7);                        // p visible before next Dijkstra
    }
    // deterministic match collection
    #pragma unroll
    for (int k = 0; k < 8; k++) {
      int r = S.p[jb0 + k];
      if (r != PFREE && r > 0) S.match_q[r - 1] = jb0 + k - 1;
    }
  }
  __syncthreads();

  // ---- Phase C: CE over matched pairs, warp-per-match, fast intrinsics ----
  if (lane == 0) { S.warp_rec[wid] = 0.0; S.warp_loc[wid] = 0.0; }
  __syncwarp();

  for (int t = wid; t < NT; t += NWARP) {
    const int q = S.match_q[t];

    // rec CE: 107 channels, 4 per lane, loaded once
    const float* rb = recb + q;
    float v4[4];
    #pragma unroll
    for (int k = 0; k < 4; k++) {
      int c = lane + (k << 5);
      v4[k] = (c < CREC) ? __ldg(rb + (size_t)c * MQ) : -INFF;
    }
    float mx = fmaxf(fmaxf(v4[0], v4[1]), fmaxf(v4[2], v4[3]));
    mx = warp_max_f(mx);
    float se = 0.f;
    #pragma unroll
    for (int k = 0; k < 4; k++) {
      int c = lane + (k << 5);
      if (c < CREC) se += __expf(v4[k] - mx);
    }
    se = warp_sum_f(se);
    float rec_term = mx + __logf(se) - __ldg(rb + (size_t)S.tgt_cls[t] * MQ);

    // loc CE: 25 channels
    const float* lb = locb + q;
    float xv  = (lane < CLOC) ? __ldg(lb + (size_t)lane * MQ) : -INFF;
    float mx2 = warp_max_f(xv);
    float se2 = warp_sum_f((lane < CLOC) ? __expf(xv - mx2) : 0.f);
    float loc_term = mx2 + __logf(se2) - __ldg(lb + (size_t)t * MQ);

    if (lane == 0) {
      S.warp_rec[wid] += (double)rec_term;
      S.warp_loc[wid] += (double)loc_term;
    }
  }
  __syncthreads();

  // ---- per-batch sums + last-block final reduction ----
  if (tid == 0) {
    double r = 0.0, l = 0.0;
    #pragma unroll
    for (int w = 0; w < NWARP; w++) { r += S.warp_rec[w]; l += S.warp_loc[w]; }
    g_sums[2 * b]     = r;
    g_sums[2 * b + 1] = l;
    __threadfence();
    unsigned old = atomicAdd(&g_count, 1u);
    S.islast = (old == BS - 1);
  }
  __syncthreads();

  if (S.islast) {
    double r = (tid < BS) ? g_sums[2 * tid]     : 0.0;
    double l = (tid < BS) ? g_sums[2 * tid + 1] : 0.0;
    #pragma unroll
    for (int o = 16; o; o >>= 1) {
      r += __shfl_xor_sync(0xffffffffu, r, o);
      l += __shfl_xor_sync(0xffffffffu, l, o);
    }
    if (lane == 0 && wid < 8) { S.red_r[wid] = r; S.red_l[wid] = l; }
    __syncthreads();
    if (tid == 0) {
      double rr = 0.0, ll = 0.0;
      #pragma unroll
      for (int w = 0; w < 4; w++) { rr += S.red_r[w]; ll += S.red_l[w]; }
      out[0] = (float)(rr / (double)(BS * NT));
      out[1] = (float)(ll / (double)(BS * NT));
      g_count = 0;   // reset for next replay
    }
  }
}

extern "C" void kernel_launch(void* const* d_in, const int* in_sizes, int n_in,
                              void* d_out, int out_size) {
  const float* rec = (const float*)d_in[0];
  const float* loc = (const float*)d_in[1];
  const int*   tgt = (const int*)d_in[2];
  float* out = (float*)d_out;

  const int smem = (int)sizeof(Smem);
  cudaFuncSetAttribute(rec_criterion_kernel,
                       cudaFuncAttributeMaxDynamicSharedMemorySize, smem);
  rec_criterion_kernel<<<BS, THREADS, smem>>>(rec, loc, tgt, out);
}

// round 14
// speedup vs baseline: 1.4135x; 1.0738x over previous
#include <cuda_runtime.h>
#include <cstdint>

#define BS    128
#define NT    25
#define MQ    1024
#define CREC  107
#define CLOC  25
#define THREADS 768
#define NWARP (THREADS / 32)
#define INFF  3.0e38f
#define PFREE 0x7fffffff

__device__ double   g_sums[BS * 2];
__device__ unsigned g_count;     // zero-init; reset by last block each launch

struct Smem {
  float  cost[NT][MQ];           // 100 KB
  unsigned long long rkey[NT];   // packed (f2ord(rowmin)<<32)|argj
  float  u[NT + 1];
  int    p[MQ + 1];
  int    way[MQ + 1];
  unsigned long long wkey[2][4]; // per-warp argmin keys, double-buffered by parity
  int    tgt_cls[NT];
  int    match_q[NT];
  int    pend[NT];
  int    npend;
  int    is64;
  double warp_rec[NWARP];
  double warp_loc[NWARP];
  int    islast;
  double red_r[8], red_l[8];
};

// focal cost via 3 MUFU (EX2, LG2, RCP). With t=e^{-x}, L=log(1+t):
//   focal = p^2 * (0.25*t^2*L - 0.75*(x+L)),  p = 1/(1+t).
__device__ __forceinline__ float focal_mufu(float x) {
  float t = __expf(-x);
  float w = 1.0f + t;
  float L = __logf(w);
  float p = __fdividef(1.0f, w);
  return p * p * (0.25f * t * t * L - 0.75f * (x + L));
}

__device__ __forceinline__ float warp_max_f(float v) {
  #pragma unroll
  for (int o = 16; o; o >>= 1) v = fmaxf(v, __shfl_xor_sync(0xffffffffu, v, o));
  return v;
}
__device__ __forceinline__ float warp_sum_f(float v) {
  #pragma unroll
  for (int o = 16; o; o >>= 1) v += __shfl_xor_sync(0xffffffffu, v, o);
  return v;
}

// float -> order-preserving uint (finite values only)
__device__ __forceinline__ unsigned f2ord(float v) {
  unsigned u = __float_as_uint(v);
  return (u & 0x80000000u) ? ~u : (u | 0x80000000u);
}
__device__ __forceinline__ float ord2f(unsigned s) {
  unsigned u = (s & 0x80000000u) ? (s & 0x7fffffffu) : ~s;
  return __uint_as_float(u);
}

__device__ __forceinline__ void bar_wg(int id) {
  asm volatile("bar.sync %0, 128;" :: "r"(id) : "memory");
}

__global__ __launch_bounds__(THREADS, 1)
void rec_criterion_kernel(const float* __restrict__ rec,
                          const float* __restrict__ loc,
                          const int*   __restrict__ tgt32,
                          float* __restrict__ out) {
  extern __shared__ char smem_raw[];
  Smem& S = *reinterpret_cast<Smem*>(smem_raw);
  const int b   = blockIdx.x;
  const int tid = threadIdx.x;
  const int wid = tid >> 5, lane = tid & 31;

  // ---- detection (warp 0) + init ----
  if (tid < 32) {
    int w = tgt32[2 * tid + 1];            // odd words of first 32 int64 slots
    unsigned bal = __ballot_sync(0xffffffffu, w != 0);
    if (tid == 0) S.is64 = (bal == 0u);
  }
  for (int j = tid; j <= MQ; j += THREADS) S.p[j] = PFREE;
  if (tid < NT) S.rkey[tid] = 0xFFFFFFFFFFFFFFFFull;
  __syncthreads();

  if (tid < NT) {
    int t;
    if (S.is64) t = (int)(reinterpret_cast<const long long*>(tgt32)[b * NT + tid]);
    else        t = tgt32[b * NT + tid];
    S.tgt_cls[tid] = t;
  }
  __syncthreads();

  const float* recb = rec + (size_t)b * CREC * MQ;
  const float* locb = loc + (size_t)b * CLOC * MQ;

  // ---- Phase A: quarter-row items (100) over 24 warps; float4; packed row-min ----
  for (int it = wid; it < 4 * NT; it += NWARP) {
    const int r = it >> 2, qh = it & 3;
    const float4* rp = reinterpret_cast<const float4*>(recb + (size_t)S.tgt_cls[r] * MQ);
    const float4* lp = reinterpret_cast<const float4*>(locb + (size_t)r * MQ);
    float4* crow4 = reinterpret_cast<float4*>(&S.cost[r][0]);
    float m = INFF; int jb = 0;
    float4 rv[2], lv[2];
    #pragma unroll
    for (int k = 0; k < 2; k++) rv[k] = __ldg(rp + lane + ((qh * 2 + k) << 5));
    #pragma unroll
    for (int k = 0; k < 2; k++) lv[k] = __ldg(lp + lane + ((qh * 2 + k) << 5));
    #pragma unroll
    for (int k = 0; k < 2; k++) {
      int g = lane + ((qh * 2 + k) << 5);      // float4 group; j = 4g..4g+3
      float4 c;
      c.x = fmaf(2.0f, focal_mufu(rv[k].x), focal_mufu(lv[k].x));
      c.y = fmaf(2.0f, focal_mufu(rv[k].y), focal_mufu(lv[k].y));
      c.z = fmaf(2.0f, focal_mufu(rv[k].z), focal_mufu(lv[k].z));
      c.w = fmaf(2.0f, focal_mufu(rv[k].w), focal_mufu(lv[k].w));
      crow4[g] = c;
      int j = g << 2;                           // ascending j per lane: first occurrence
      if (c.x < m) { m = c.x; jb = j; }
      if (c.y < m) { m = c.y; jb = j + 1; }
      if (c.z < m) { m = c.z; jb = j + 2; }
      if (c.w < m) { m = c.w; jb = j + 3; }
    }
    unsigned om = __reduce_min_sync(0xffffffffu, f2ord(m));
    float gm = ord2f(om);
    unsigned jc = (m == gm) ? (unsigned)jb : 0xffffffffu;
    unsigned jm = __reduce_min_sync(0xffffffffu, jc);
    if (lane == 0)
      atomicMin(&S.rkey[r], ((unsigned long long)om << 32) | (unsigned long long)jm);
  }
  __syncthreads();

  // ---- Phase B1: greedy init, parallel (atomicMin = first-row-wins) ----
  if (tid < 32) {
    bool has = tid < NT;
    int rarg = 0;
    if (has) {
      unsigned long long key = S.rkey[tid];
      rarg = (int)(key & 0xffffffffu);
      S.u[tid + 1] = ord2f((unsigned)(key >> 32));
      atomicMin(&S.p[rarg + 1], tid + 1);
    }
    if (tid == 0) S.u[0] = 0.0f;
    __syncwarp();
    bool lost = has && (S.p[rarg + 1] != tid + 1);
    unsigned mask = __ballot_sync(0xffffffffu, lost);
    if (lost) S.pend[__popc(mask & ((1u << tid) - 1u))] = tid + 1;  // ascending rows
    if (tid == 0) S.npend = __popc(mask);
  }
  __syncthreads();

  // ---- Phase B2: Dijkstra for contested rows — 4-warp workgroup, cached p ----
  // tid owns 8 contiguous cols j in [8*tid+1, 8*tid+8]; j-order == (tid,k)-order.
  // prow_pk: 8x8-bit cached rows for owned cols (255 = free).
  if (tid < 128) {
    const int jb0 = (tid << 3) + 1;
    float v_r[8];
    #pragma unroll
    for (int k = 0; k < 8; k++) v_r[k] = 0.0f;
    unsigned long long prow_pk = 0;
    #pragma unroll
    for (int k = 0; k < 8; k++) {
      int r = S.p[jb0 + k];
      prow_pk |= (unsigned long long)((r == PFREE) ? 255u : (unsigned)r) << (k * 8);
    }
    const int np = S.npend;

    for (int pi = 0; pi < np; pi++) {
      const int i = S.pend[pi];
      float minv_r[8];
      #pragma unroll
      for (int k = 0; k < 8; k++) minv_r[k] = INFF;
      unsigned usedmask = 0u;
      float D = 0.0f;
      int j0 = 0, i0 = i, it = 0;

      while (true) {
        if (j0 > 0 && ((j0 - 1) >> 3) == tid) usedmask |= 1u << ((j0 - 1) & 7);

        const float u0p = S.u[i0] - D;
        const float4* crow4 =
            reinterpret_cast<const float4*>(&S.cost[i0 - 1][0]) + (tid << 1);

        float bv = INFF; int bk = 0;
        #pragma unroll
        for (int q = 0; q < 2; q++) {
          float4 cv = crow4[q];
          const int kq = q << 2;
          {
            int k = kq;     bool used = (usedmask >> k) & 1u;
            float cur = (cv.x - u0p) - v_r[k];
            cur = used ? INFF : cur;
            if (cur < minv_r[k]) { S.way[jb0 + k] = j0; minv_r[k] = cur; }
            float mv = used ? INFF : minv_r[k];
            if (mv < bv) { bv = mv; bk = k; }
          }
          {
            int k = kq + 1; bool used = (usedmask >> k) & 1u;
            float cur = (cv.y - u0p) - v_r[k];
            cur = used ? INFF : cur;
            if (cur < minv_r[k]) { S.way[jb0 + k] = j0; minv_r[k] = cur; }
            float mv = used ? INFF : minv_r[k];
            if (mv < bv) { bv = mv; bk = k; }
          }
          {
            int k = kq + 2; bool used = (usedmask >> k) & 1u;
            float cur = (cv.z - u0p) - v_r[k];
            cur = used ? INFF : cur;
            if (cur < minv_r[k]) { S.way[jb0 + k] = j0; minv_r[k] = cur; }
            float mv = used ? INFF : minv_r[k];
            if (mv < bv) { bv = mv; bk = k; }
          }
          {
            int k = kq + 3; bool used = (usedmask >> k) & 1u;
            float cur = (cv.w - u0p) - v_r[k];
            cur = used ? INFF : cur;
            if (cur < minv_r[k]) { S.way[jb0 + k] = j0; minv_r[k] = cur; }
            float mv = used ? INFF : minv_r[k];
            if (mv < bv) { bv = mv; bk = k; }
          }
        }
        // pack local key: low = (j<<8)|(row<<1)|free  (row/free below j keeps (ord,j) order)
        unsigned rloc = (unsigned)((prow_pk >> (bk * 8)) & 0xffu);   // 255 = free
        unsigned lowloc = ((unsigned)(jb0 + bk) << 8) |
                          ((rloc == 255u) ? 1u : (rloc << 1));
        unsigned ov = f2ord(bv);
        unsigned om = __reduce_min_sync(0xffffffffu, ov);
        unsigned ll = (ov == om) ? lowloc : 0xffffffffu;
        unsigned lm = __reduce_min_sync(0xffffffffu, ll);
        const int par = it & 1;
        if (lane == 0)
          S.wkey[par][wid] = ((unsigned long long)om << 32) | (unsigned long long)lm;
        bar_wg(7);
        unsigned long long k0 = S.wkey[par][0], k1 = S.wkey[par][1];
        unsigned long long k2 = S.wkey[par][2], k3 = S.wkey[par][3];
        unsigned long long km = k0 < k1 ? k0 : k1;
        if (k2 < km) km = k2;
        if (k3 < km) km = k3;
        D = ord2f((unsigned)(km >> 32));
        unsigned lo = (unsigned)km;
        j0 = (int)((lo >> 8) & 2047u);
        it++;
        if (lo & 1u) break;               // free column reached (all threads agree)
        i0 = (int)((lo >> 1) & 0x3fu);    // row assigned to j0 (from cached key)
      }

      const float Dend = D;
      // fixups: used col k entered the tree at absolute distance minv_r[k]
      unsigned mm = usedmask;
      while (mm) {
        int k = __ffs(mm) - 1; mm &= mm - 1;
        float dv = Dend - minv_r[k];
        v_r[k] -= dv;
        int r = (int)((prow_pk >> (k * 8)) & 0xffu);   // always assigned (1..25)
        S.u[r] += dv;                    // distinct rows per used col -> race-free
      }
      if (tid == 0) {
        S.u[i] += Dend;
        S.p[0] = i;
        int j = j0;                      // augment through way[]
        while (j != 0) { int jp = S.way[j]; S.p[j] = S.p[jp]; j = jp; }
      }
      bar_wg(7);                          // p visible; u visible
      // refresh cached rows (p changed along the augmenting path)
      prow_pk = 0;
      #pragma unroll
      for (int k = 0; k < 8; k++) {
        int r = S.p[jb0 + k];
        prow_pk |= (unsigned long long)((r == PFREE) ? 255u : (unsigned)r) << (k * 8);
      }
    }
    // deterministic match collection
    #pragma unroll
    for (int k = 0; k < 8; k++) {
      int r = S.p[jb0 + k];
      if (r != PFREE && r > 0) S.match_q[r - 1] = jb0 + k - 1;
    }
  }
  __syncthreads();

  // ---- Phase C: CE over matched pairs, warp-per-match, fast intrinsics ----
  if (lane == 0) { S.warp_rec[wid] = 0.0; S.warp_loc[wid] = 0.0; }
  __syncwarp();

  for (int t = wid; t < NT; t += NWARP) {
    const int q = S.match_q[t];

    // rec CE: 107 channels, 4 per lane, loaded once
    const float* rb = recb + q;
    float v4[4];
    #pragma unroll
    for (int k = 0; k < 4; k++) {
      int c = lane + (k << 5);
      v4[k] = (c < CREC) ? __ldg(rb + (size_t)c * MQ) : -INFF;
    }
    float mx = fmaxf(fmaxf(v4[0], v4[1]), fmaxf(v4[2], v4[3]));
    mx = warp_max_f(mx);
    float se = 0.f;
    #pragma unroll
    for (int k = 0; k < 4; k++) {
      int c = lane + (k << 5);
      if (c < CREC) se += __expf(v4[k] - mx);
    }
    se = warp_sum_f(se);
    float rec_term = mx + __logf(se) - __ldg(rb + (size_t)S.tgt_cls[t] * MQ);

    // loc CE: 25 channels
    const float* lb = locb + q;
    float xv  = (lane < CLOC) ? __ldg(lb + (size_t)lane * MQ) : -INFF;
    float mx2 = warp_max_f(xv);
    float se2 = warp_sum_f((lane < CLOC) ? __expf(xv - mx2) : 0.f);
    float loc_term = mx2 + __logf(se2) - __ldg(lb + (size_t)t * MQ);

    if (lane == 0) {
      S.warp_rec[wid] += (double)rec_term;
      S.warp_loc[wid] += (double)loc_term;
    }
  }
  __syncthreads();

  // ---- per-batch sums + last-block final reduction ----
  if (tid == 0) {
    double r = 0.0, l = 0.0;
    #pragma unroll
    for (int w = 0; w < NWARP; w++) { r += S.warp_rec[w]; l += S.warp_loc[w]; }
    g_sums[2 * b]     = r;
    g_sums[2 * b + 1] = l;
    __threadfence();
    unsigned old = atomicAdd(&g_count, 1u);
    S.islast = (old == BS - 1);
  }
  __syncthreads();

  if (S.islast) {
    double r = (tid < BS) ? g_sums[2 * tid]     : 0.0;
    double l = (tid < BS) ? g_sums[2 * tid + 1] : 0.0;
    #pragma unroll
    for (int o = 16; o; o >>= 1) {
      r += __shfl_xor_sync(0xffffffffu, r, o);
      l += __shfl_xor_sync(0xffffffffu, l, o);
    }
    if (lane == 0 && wid < 8) { S.red_r[wid] = r; S.red_l[wid] = l; }
    __syncthreads();
    if (tid == 0) {
      double rr = 0.0, ll = 0.0;
      #pragma unroll
      for (int w = 0; w < 4; w++) { rr += S.red_r[w]; ll += S.red_l[w]; }
      out[0] = (float)(rr / (double)(BS * NT));
      out[1] = (float)(ll / (double)(BS * NT));
      g_count = 0;   // reset for next replay
    }
  }
}

extern "C" void kernel_launch(void* const* d_in, const int* in_sizes, int n_in,
                              void* d_out, int out_size) {
  const float* rec = (const float*)d_in[0];
  const float* loc = (const float*)d_in[1];
  const int*   tgt = (const int*)d_in[2];
  float* out = (float*)d_out;

  const int smem = (int)sizeof(Smem);
  cudaFuncSetAttribute(rec_criterion_kernel,
                       cudaFuncAttributeMaxDynamicSharedMemorySize, smem);
  rec_criterion_kernel<<<BS, THREADS, smem>>>(rec, loc, tgt, out);
}

// round 15
// speedup vs baseline: 1.5431x; 1.0917x over previous
#include <cuda_runtime.h>
#include <cstdint>

#define BS    128
#define NT    25
#define MQ    1024
#define CREC  107
#define CLOC  25
#define THREADS 768
#define NWARP (THREADS / 32)
#define INFF  3.0e38f
#define PFREE 0x7fffffff

__device__ double   g_sums[BS * 2];
__device__ unsigned g_count;     // zero-init; reset by last block each launch

struct Smem {
  float  cost[NT][MQ];           // 100 KB
  unsigned long long rkey[NT];   // packed (f2ord(rowmin)<<32)|argj
  float  u[NT + 1];
  int    p[MQ + 1];
  int    way[MQ + 1];
  unsigned long long wkey[2][4]; // per-warp argmin keys, double-buffered by parity
  int    tgt_cls[NT];
  int    match_q[NT];
  int    qs_used[NT];            // greedy (speculative) query per row, -1 if pending
  float  rec_t[NT], loc_t[NT];   // per-row CE terms
  int    pend[NT];
  int    npend;
  int    is64;
  int    islast;
  double red_r[4], red_l[4];
};

// focal cost via 3 MUFU (EX2, LG2, RCP). With t=e^{-x}, L=log(1+t):
//   focal = p^2 * (0.25*t^2*L - 0.75*(x+L)),  p = 1/(1+t).
__device__ __forceinline__ float focal_mufu(float x) {
  float t = __expf(-x);
  float w = 1.0f + t;
  float L = __logf(w);
  float p = __fdividef(1.0f, w);
  return p * p * (0.25f * t * t * L - 0.75f * (x + L));
}

__device__ __forceinline__ float warp_max_f(float v) {
  #pragma unroll
  for (int o = 16; o; o >>= 1) v = fmaxf(v, __shfl_xor_sync(0xffffffffu, v, o));
  return v;
}
__device__ __forceinline__ float warp_sum_f(float v) {
  #pragma unroll
  for (int o = 16; o; o >>= 1) v += __shfl_xor_sync(0xffffffffu, v, o);
  return v;
}
__device__ __forceinline__ double warp_sum_d(double v) {
  #pragma unroll
  for (int o = 16; o; o >>= 1) v += __shfl_xor_sync(0xffffffffu, v, o);
  return v;
}

// float -> order-preserving uint (finite values only)
__device__ __forceinline__ unsigned f2ord(float v) {
  unsigned u = __float_as_uint(v);
  return (u & 0x80000000u) ? ~u : (u | 0x80000000u);
}
__device__ __forceinline__ float ord2f(unsigned s) {
  unsigned u = (s & 0x80000000u) ? (s & 0x7fffffffu) : ~s;
  return __uint_as_float(u);
}

__device__ __forceinline__ void bar_wg(int id) {
  asm volatile("bar.sync %0, 128;" :: "r"(id) : "memory");
}

// CE terms for one matched (row t, query q): rec CE + loc CE, warp-collective.
__device__ __forceinline__ void ce_pair(const float* __restrict__ recb,
                                        const float* __restrict__ locb,
                                        int t, int q, int tcls, int lane,
                                        float& rec_term, float& loc_term) {
  const float* rb = recb + q;
  float v4[4];
  #pragma unroll
  for (int k = 0; k < 4; k++) {
    int c = lane + (k << 5);
    v4[k] = (c < CREC) ? __ldg(rb + (size_t)c * MQ) : -INFF;
  }
  float mx = fmaxf(fmaxf(v4[0], v4[1]), fmaxf(v4[2], v4[3]));
  mx = warp_max_f(mx);
  float se = 0.f;
  #pragma unroll
  for (int k = 0; k < 4; k++) {
    int c = lane + (k << 5);
    if (c < CREC) se += __expf(v4[k] - mx);
  }
  se = warp_sum_f(se);
  rec_term = mx + __logf(se) - __ldg(rb + (size_t)tcls * MQ);

  const float* lb = locb + q;
  float xv  = (lane < CLOC) ? __ldg(lb + (size_t)lane * MQ) : -INFF;
  float mx2 = warp_max_f(xv);
  float se2 = warp_sum_f((lane < CLOC) ? __expf(xv - mx2) : 0.f);
  loc_term = mx2 + __logf(se2) - __ldg(lb + (size_t)t * MQ);
}

__global__ __launch_bounds__(THREADS, 1)
void rec_criterion_kernel(const float* __restrict__ rec,
                          const float* __restrict__ loc,
                          const int*   __restrict__ tgt32,
                          float* __restrict__ out) {
  extern __shared__ char smem_raw[];
  Smem& S = *reinterpret_cast<Smem*>(smem_raw);
  const int b   = blockIdx.x;
  const int tid = threadIdx.x;
  const int wid = tid >> 5, lane = tid & 31;

  // ---- detection (warp 0) + init ----
  if (tid < 32) {
    int w = tgt32[2 * tid + 1];            // odd words of first 32 int64 slots
    unsigned bal = __ballot_sync(0xffffffffu, w != 0);
    if (tid == 0) S.is64 = (bal == 0u);
  }
  for (int j = tid; j <= MQ; j += THREADS) S.p[j] = PFREE;
  if (tid < NT) S.rkey[tid] = 0xFFFFFFFFFFFFFFFFull;
  __syncthreads();

  if (tid < NT) {
    int t;
    if (S.is64) t = (int)(reinterpret_cast<const long long*>(tgt32)[b * NT + tid]);
    else        t = tgt32[b * NT + tid];
    S.tgt_cls[tid] = t;
  }
  __syncthreads();

  const float* recb = rec + (size_t)b * CREC * MQ;
  const float* locb = loc + (size_t)b * CLOC * MQ;

  // ---- Phase A: quarter-row items (100) over 24 warps; float4; packed row-min ----
  for (int it = wid; it < 4 * NT; it += NWARP) {
    const int r = it >> 2, qh = it & 3;
    const float4* rp = reinterpret_cast<const float4*>(recb + (size_t)S.tgt_cls[r] * MQ);
    const float4* lp = reinterpret_cast<const float4*>(locb + (size_t)r * MQ);
    float4* crow4 = reinterpret_cast<float4*>(&S.cost[r][0]);
    float m = INFF; int jb = 0;
    float4 rv[2], lv[2];
    #pragma unroll
    for (int k = 0; k < 2; k++) rv[k] = __ldg(rp + lane + ((qh * 2 + k) << 5));
    #pragma unroll
    for (int k = 0; k < 2; k++) lv[k] = __ldg(lp + lane + ((qh * 2 + k) << 5));
    #pragma unroll
    for (int k = 0; k < 2; k++) {
      int g = lane + ((qh * 2 + k) << 5);      // float4 group; j = 4g..4g+3
      float4 c;
      c.x = fmaf(2.0f, focal_mufu(rv[k].x), focal_mufu(lv[k].x));
      c.y = fmaf(2.0f, focal_mufu(rv[k].y), focal_mufu(lv[k].y));
      c.z = fmaf(2.0f, focal_mufu(rv[k].z), focal_mufu(lv[k].z));
      c.w = fmaf(2.0f, focal_mufu(rv[k].w), focal_mufu(lv[k].w));
      crow4[g] = c;
      int j = g << 2;                           // ascending j per lane: first occurrence
      if (c.x < m) { m = c.x; jb = j; }
      if (c.y < m) { m = c.y; jb = j + 1; }
      if (c.z < m) { m = c.z; jb = j + 2; }
      if (c.w < m) { m = c.w; jb = j + 3; }
    }
    unsigned om = __reduce_min_sync(0xffffffffu, f2ord(m));
    float gm = ord2f(om);
    unsigned jc = (m == gm) ? (unsigned)jb : 0xffffffffu;
    unsigned jm = __reduce_min_sync(0xffffffffu, jc);
    if (lane == 0)
      atomicMin(&S.rkey[r], ((unsigned long long)om << 32) | (unsigned long long)jm);
  }
  __syncthreads();

  // ---- Phase B1: greedy init, parallel; also publish speculative q per row ----
  if (tid < 32) {
    bool has = tid < NT;
    int rarg = 0;
    if (has) {
      unsigned long long key = S.rkey[tid];
      rarg = (int)(key & 0xffffffffu);
      S.u[tid + 1] = ord2f((unsigned)(key >> 32));
      atomicMin(&S.p[rarg + 1], tid + 1);
    }
    if (tid == 0) S.u[0] = 0.0f;
    __syncwarp();
    bool lost = has && (S.p[rarg + 1] != tid + 1);
    unsigned mask = __ballot_sync(0xffffffffu, lost);
    if (lost) S.pend[__popc(mask & ((1u << tid) - 1u))] = tid + 1;  // ascending rows
    if (has) S.qs_used[tid] = lost ? -1 : rarg;   // speculation target (no race: pre-B2)
    if (tid == 0) S.npend = __popc(mask);
  }
  __syncthreads();

  if (wid < 4) {
    // ---- Phase B2: Dijkstra for contested rows — 4-warp workgroup, cached p ----
    // tid owns 8 contiguous cols j in [8*tid+1, 8*tid+8]; j-order == (tid,k)-order.
    const int jb0 = (tid << 3) + 1;
    float v_r[8];
    #pragma unroll
    for (int k = 0; k < 8; k++) v_r[k] = 0.0f;
    unsigned long long prow_pk = 0;
    #pragma unroll
    for (int k = 0; k < 8; k++) {
      int r = S.p[jb0 + k];
      prow_pk |= (unsigned long long)((r == PFREE) ? 255u : (unsigned)r) << (k * 8);
    }
    const int np = S.npend;

    for (int pi = 0; pi < np; pi++) {
      const int i = S.pend[pi];
      float minv_r[8];
      #pragma unroll
      for (int k = 0; k < 8; k++) minv_r[k] = INFF;
      unsigned usedmask = 0u;
      float D = 0.0f;
      int j0 = 0, i0 = i, it = 0;

      while (true) {
        if (j0 > 0 && ((j0 - 1) >> 3) == tid) usedmask |= 1u << ((j0 - 1) & 7);

        const float u0p = S.u[i0] - D;
        const float4* crow4 =
            reinterpret_cast<const float4*>(&S.cost[i0 - 1][0]) + (tid << 1);

        float bv = INFF; int bk = 0;
        #pragma unroll
        for (int q = 0; q < 2; q++) {
          float4 cv = crow4[q];
          const int kq = q << 2;
          {
            int k = kq;     bool used = (usedmask >> k) & 1u;
            float cur = (cv.x - u0p) - v_r[k];
            cur = used ? INFF : cur;
            if (cur < minv_r[k]) { S.way[jb0 + k] = j0; minv_r[k] = cur; }
            float mv = used ? INFF : minv_r[k];
            if (mv < bv) { bv = mv; bk = k; }
          }
          {
            int k = kq + 1; bool used = (usedmask >> k) & 1u;
            float cur = (cv.y - u0p) - v_r[k];
            cur = used ? INFF : cur;
            if (cur < minv_r[k]) { S.way[jb0 + k] = j0; minv_r[k] = cur; }
            float mv = used ? INFF : minv_r[k];
            if (mv < bv) { bv = mv; bk = k; }
          }
          {
            int k = kq + 2; bool used = (usedmask >> k) & 1u;
            float cur = (cv.z - u0p) - v_r[k];
            cur = used ? INFF : cur;
            if (cur < minv_r[k]) { S.way[jb0 + k] = j0; minv_r[k] = cur; }
            float mv = used ? INFF : minv_r[k];
            if (mv < bv) { bv = mv; bk = k; }
          }
          {
            int k = kq + 3; bool used = (usedmask >> k) & 1u;
            float cur = (cv.w - u0p) - v_r[k];
            cur = used ? INFF : cur;
            if (cur < minv_r[k]) { S.way[jb0 + k] = j0; minv_r[k] = cur; }
            float mv = used ? INFF : minv_r[k];
            if (mv < bv) { bv = mv; bk = k; }
          }
        }
        // pack local key: low = (j<<8)|(row<<1)|free  (row/free below j keeps (ord,j) order)
        unsigned rloc = (unsigned)((prow_pk >> (bk * 8)) & 0xffu);   // 255 = free
        unsigned lowloc = ((unsigned)(jb0 + bk) << 8) |
                          ((rloc == 255u) ? 1u : (rloc << 1));
        unsigned ov = f2ord(bv);
        unsigned om = __reduce_min_sync(0xffffffffu, ov);
        unsigned ll = (ov == om) ? lowloc : 0xffffffffu;
        unsigned lm = __reduce_min_sync(0xffffffffu, ll);
        const int par = it & 1;
        if (lane == 0)
          S.wkey[par][wid] = ((unsigned long long)om << 32) | (unsigned long long)lm;
        bar_wg(7);
        unsigned long long k0 = S.wkey[par][0], k1 = S.wkey[par][1];
        unsigned long long k2 = S.wkey[par][2], k3 = S.wkey[par][3];
        unsigned long long km = k0 < k1 ? k0 : k1;
        if (k2 < km) km = k2;
        if (k3 < km) km = k3;
        D = ord2f((unsigned)(km >> 32));
        unsigned lo = (unsigned)km;
        j0 = (int)((lo >> 8) & 2047u);
        it++;
        if (lo & 1u) break;               // free column reached (all threads agree)
        i0 = (int)((lo >> 1) & 0x3fu);    // row assigned to j0 (from cached key)
      }

      const float Dend = D;
      // fixups: used col k entered the tree at absolute distance minv_r[k]
      unsigned mm = usedmask;
      while (mm) {
        int k = __ffs(mm) - 1; mm &= mm - 1;
        float dv = Dend - minv_r[k];
        v_r[k] -= dv;
        int r = (int)((prow_pk >> (k * 8)) & 0xffu);   // always assigned (1..25)
        S.u[r] += dv;                    // distinct rows per used col -> race-free
      }
      if (tid == 0) {
        S.u[i] += Dend;
        S.p[0] = i;
        int j = j0;                      // augment through way[]
        while (j != 0) { int jp = S.way[j]; S.p[j] = S.p[jp]; j = jp; }
      }
      bar_wg(7);                          // p visible; u visible
      // refresh cached rows (p changed along the augmenting path)
      prow_pk = 0;
      #pragma unroll
      for (int k = 0; k < 8; k++) {
        int r = S.p[jb0 + k];
        prow_pk |= (unsigned long long)((r == PFREE) ? 255u : (unsigned)r) << (k * 8);
      }
    }
    // deterministic match collection
    #pragma unroll
    for (int k = 0; k < 8; k++) {
      int r = S.p[jb0 + k];
      if (r != PFREE && r > 0) S.match_q[r - 1] = jb0 + k - 1;
    }
  } else {
    // ---- Phase C (speculative): warps 4..23 compute CE for greedy-matched rows
    // concurrently with B2. Reads: qs_used/tgt_cls (stable), global rec/loc.
    for (int t = wid - 4; t < NT; t += NWARP - 4) {
      int q = S.qs_used[t];
      if (q >= 0) {
        float rt, lt;
        ce_pair(recb, locb, t, q, S.tgt_cls[t], lane, rt, lt);
        if (lane == 0) { S.rec_t[t] = rt; S.loc_t[t] = lt; }
      }
    }
  }
  __syncthreads();

  // ---- Phase C fixup: recompute rows whose final q differs from speculation ----
  for (int t = wid; t < NT; t += NWARP) {
    const int q = S.match_q[t];
    if (q != S.qs_used[t]) {
      float rt, lt;
      ce_pair(recb, locb, t, q, S.tgt_cls[t], lane, rt, lt);
      if (lane == 0) { S.rec_t[t] = rt; S.loc_t[t] = lt; }
    }
  }
  __syncthreads();

  // ---- per-batch sums (warp 0, fixed deterministic order) + last-block reduce ----
  if (tid < 32) {
    double r = (lane < NT) ? (double)S.rec_t[lane] : 0.0;
    double l = (lane < NT) ? (double)S.loc_t[lane] : 0.0;
    r = warp_sum_d(r);
    l = warp_sum_d(l);
    if (lane == 0) {
      g_sums[2 * b]     = r;
      g_sums[2 * b + 1] = l;
      __threadfence();
      unsigned old = atomicAdd(&g_count, 1u);
      S.islast = (old == BS - 1);
    }
  }
  __syncthreads();

  if (S.islast) {
    double r = (tid < BS) ? g_sums[2 * tid]     : 0.0;
    double l = (tid < BS) ? g_sums[2 * tid + 1] : 0.0;
    r = warp_sum_d(r);
    l = warp_sum_d(l);
    if (lane == 0 && wid < 4) { S.red_r[wid] = r; S.red_l[wid] = l; }
    __syncthreads();
    if (tid == 0) {
      double rr = S.red_r[0] + S.red_r[1] + S.red_r[2] + S.red_r[3];
      double ll = S.red_l[0] + S.red_l[1] + S.red_l[2] + S.red_l[3];
      out[0] = (float)(rr / (double)(BS * NT));
      out[1] = (float)(ll / (double)(BS * NT));
      g_count = 0;   // reset for next replay
    }
  }
}

extern "C" void kernel_launch(void* const* d_in, const int* in_sizes, int n_in,
                              void* d_out, int out_size) {
  const float* rec = (const float*)d_in[0];
  const float* loc = (const float*)d_in[1];
  const int*   tgt = (const int*)d_in[2];
  float* out = (float*)d_out;

  const int smem = (int)sizeof(Smem);
  cudaFuncSetAttribute(rec_criterion_kernel,
                       cudaFuncAttributeMaxDynamicSharedMemorySize, smem);
  rec_criterion_kernel<<<BS, THREADS, smem>>>(rec, loc, tgt, out);
}